// round 3
// baseline (speedup 1.0000x reference)
#include <cuda_runtime.h>
#include <cuda_bf16.h>
#include <cstddef>

// LINKX forward:
//   hx = relu(x@wx1+bx1)@wx2+bx2
//   agg = segment_mean(adj_embed[src] -> dst)
//   ha = relu(agg@wa1+ba1)@wa2+ba2
//   h = relu(relu([hx,ha]@ww1+bw1) + hx + ha)
//   out = h@wc+bc

#define NN     100000
#define EE     1600000
#define INDIM  256
#define HID    128
#define NC     40

// ---------------- static scratch (no allocations allowed) ----------------
__device__ float g_tmp [(size_t)NN * HID];     // relu(x@wx1) then relu(aggN@wa1)
__device__ float g_comb[(size_t)NN * 2 * HID]; // [hx | ha]
__device__ float g_agg [(size_t)NN * HID];
__device__ float g_h   [(size_t)NN * HID];
__device__ float g_deg [NN];                   // deg, then 1/max(deg,1)

// ---------------- helpers ----------------
__device__ __forceinline__ void red_add_v4(float* addr, float4 v) {
    asm volatile("red.global.add.v4.f32 [%0], {%1,%2,%3,%4};"
                 :: "l"(addr), "f"(v.x), "f"(v.y), "f"(v.z), "f"(v.w)
                 : "memory");
}
__device__ __forceinline__ float relu(float v) { return fmaxf(v, 0.0f); }

// ---------------- zero agg + deg ----------------
__global__ void zero_kernel() {
    int idx = blockIdx.x * blockDim.x + threadIdx.x;
    if (idx < NN * HID) g_agg[idx] = 0.0f;
    if (idx < NN) g_deg[idx] = 0.0f;
}

// ---------------- edge scatter: warp per edge ----------------
__global__ void scatter_kernel(const int* __restrict__ ei,
                               const float* __restrict__ z) {
    int gw   = (blockIdx.x * blockDim.x + threadIdx.x) >> 5;
    int lane = threadIdx.x & 31;
    if (gw >= EE) return;
    int s = ei[gw];
    int d = ei[EE + gw];
    float4 v = *((const float4*)(z + (size_t)s * HID) + lane);
    red_add_v4(g_agg + (size_t)d * HID + lane * 4, v);
    if (lane == 0) atomicAdd(&g_deg[d], 1.0f);
}

// ---------------- deg -> 1/max(deg,1) ----------------
__global__ void rdeg_kernel() {
    int i = blockIdx.x * blockDim.x + threadIdx.x;
    if (i < NN) g_deg[i] = 1.0f / fmaxf(g_deg[i], 1.0f);
}

// ---------------- generic 128-col GEMM, 128x128 tile, 8x8 per thread ------
// MODE 0: C = acc + bias
// MODE 1: C = relu(acc + bias)
// MODE 2: C = relu(relu(acc + bias) + res[r][c] + res[r][c+128])   (res ld=256)
#define BM 128
#define BN 128
#define BK 16

template <int MODE>
__global__ __launch_bounds__(256, 2)
void gemm_n128(const float* __restrict__ A, const float* __restrict__ W,
               const float* __restrict__ bias, float* __restrict__ C,
               int M, int K, int ldc,
               const float* __restrict__ rowscale,
               const float* __restrict__ res) {
    __shared__ float As[BK][BM + 4];   // [k][row], padded
    __shared__ float Bs[BK][BN];       // [k][col]

    int tid = threadIdx.x;
    int block_row = blockIdx.x * BM;
    int tx = tid & 15;        // col group (8 cols each)
    int ty = tid >> 4;        // row group (8 rows each)

    float acc[8][8];
#pragma unroll
    for (int i = 0; i < 8; i++)
#pragma unroll
        for (int j = 0; j < 8; j++) acc[i][j] = 0.0f;

    for (int kt = 0; kt < K; kt += BK) {
        // A tile: 128 rows x 16 cols = 512 float4, 2 per thread, store transposed
#pragma unroll
        for (int i = 0; i < 2; i++) {
            int f = tid + i * 256;
            int r  = f >> 2;
            int c4 = (f & 3) * 4;
            int gr = block_row + r;
            float4 v = make_float4(0.f, 0.f, 0.f, 0.f);
            float s = 1.0f;
            if (gr < M) {
                v = *(const float4*)(A + (size_t)gr * K + kt + c4);
                if (rowscale) s = rowscale[gr];
            }
            As[c4 + 0][r] = v.x * s;
            As[c4 + 1][r] = v.y * s;
            As[c4 + 2][r] = v.z * s;
            As[c4 + 3][r] = v.w * s;
        }
        // B tile: 16 rows x 128 cols = 512 float4, 2 per thread
#pragma unroll
        for (int i = 0; i < 2; i++) {
            int f = tid + i * 256;
            int r  = f >> 5;
            int c4 = (f & 31) * 4;
            *(float4*)&Bs[r][c4] = *(const float4*)(W + (size_t)(kt + r) * BN + c4);
        }
        __syncthreads();

#pragma unroll
        for (int k = 0; k < BK; k++) {
            float a[8], b[8];
            *(float4*)&a[0] = *(const float4*)&As[k][ty * 8];
            *(float4*)&a[4] = *(const float4*)&As[k][ty * 8 + 4];
            *(float4*)&b[0] = *(const float4*)&Bs[k][tx * 8];
            *(float4*)&b[4] = *(const float4*)&Bs[k][tx * 8 + 4];
#pragma unroll
            for (int i = 0; i < 8; i++)
#pragma unroll
                for (int j = 0; j < 8; j++)
                    acc[i][j] = fmaf(a[i], b[j], acc[i][j]);
        }
        __syncthreads();
    }

    // epilogue
#pragma unroll
    for (int i = 0; i < 8; i++) {
        int r = block_row + ty * 8 + i;
        if (r >= M) continue;
#pragma unroll
        for (int j4 = 0; j4 < 2; j4++) {
            int c = tx * 8 + j4 * 4;
            float4 o;
            o.x = acc[i][j4 * 4 + 0] + bias[c + 0];
            o.y = acc[i][j4 * 4 + 1] + bias[c + 1];
            o.z = acc[i][j4 * 4 + 2] + bias[c + 2];
            o.w = acc[i][j4 * 4 + 3] + bias[c + 3];
            if (MODE >= 1) {
                o.x = relu(o.x); o.y = relu(o.y); o.z = relu(o.z); o.w = relu(o.w);
            }
            if (MODE == 2) {
                const float* rr = res + (size_t)r * 256 + c;
                float4 r1 = *(const float4*)rr;
                float4 r2 = *(const float4*)(rr + 128);
                o.x = relu(o.x + r1.x + r2.x);
                o.y = relu(o.y + r1.y + r2.y);
                o.z = relu(o.z + r1.z + r2.z);
                o.w = relu(o.w + r1.w + r2.w);
            }
            *(float4*)(C + (size_t)r * ldc + c) = o;
        }
    }
}

// ---------------- classifier GEMM: [M,128] @ [128,40] + b ----------------
__global__ __launch_bounds__(256, 2)
void gemm_n40(const float* __restrict__ A, const float* __restrict__ W,
              const float* __restrict__ bias, float* __restrict__ C, int M) {
    __shared__ float As[64][132];
    __shared__ float Ws[128 * 40];
    __shared__ float bs[40];

    int tid = threadIdx.x;
    int br  = blockIdx.x * 64;

    for (int i = tid; i < 128 * 40; i += 256) Ws[i] = W[i];
    if (tid < 40) bs[tid] = bias[tid];
    for (int i = tid; i < 64 * 32; i += 256) {
        int r  = i >> 5;
        int c4 = (i & 31) * 4;
        int gr = br + r;
        float4 v = make_float4(0.f, 0.f, 0.f, 0.f);
        if (gr < M) v = *(const float4*)(A + (size_t)gr * HID + c4);
        *(float4*)&As[r][c4] = v;
    }
    __syncthreads();

    int r = tid >> 2;
    int q = tid & 3;          // 10 cols each
    float acc[10];
#pragma unroll
    for (int j = 0; j < 10; j++) acc[j] = 0.0f;

    for (int k = 0; k < 128; k += 4) {
        float4 a = *(const float4*)&As[r][k];
        float av[4] = {a.x, a.y, a.z, a.w};
#pragma unroll
        for (int kk = 0; kk < 4; kk++) {
            const float* wrow = &Ws[(k + kk) * 40 + q * 10];
#pragma unroll
            for (int j = 0; j < 10; j++)
                acc[j] = fmaf(av[kk], wrow[j], acc[j]);
        }
    }

    int gr = br + r;
    if (gr < M) {
        float* o = C + (size_t)gr * NC + q * 10;
#pragma unroll
        for (int j = 0; j < 10; j++) o[j] = acc[j] + bs[q * 10 + j];
    }
}

// ---------------- host launch ----------------
extern "C" void kernel_launch(void* const* d_in, const int* in_sizes, int n_in,
                              void* d_out, int out_size) {
    const float* x    = (const float*)d_in[0];
    const int*   ei   = (const int*)  d_in[1];
    const float* adj  = (const float*)d_in[2];
    const float* wx1  = (const float*)d_in[3];
    const float* bx1  = (const float*)d_in[4];
    const float* wx2  = (const float*)d_in[5];
    const float* bx2  = (const float*)d_in[6];
    const float* wa1  = (const float*)d_in[7];
    const float* ba1  = (const float*)d_in[8];
    const float* wa2  = (const float*)d_in[9];
    const float* ba2  = (const float*)d_in[10];
    const float* ww1  = (const float*)d_in[11];
    const float* bw1  = (const float*)d_in[12];
    const float* wc   = (const float*)d_in[13];
    const float* bc   = (const float*)d_in[14];
    float* out = (float*)d_out;

    float *tmp, *comb, *agg, *h, *deg;
    cudaGetSymbolAddress((void**)&tmp,  g_tmp);
    cudaGetSymbolAddress((void**)&comb, g_comb);
    cudaGetSymbolAddress((void**)&agg,  g_agg);
    cudaGetSymbolAddress((void**)&h,    g_h);
    cudaGetSymbolAddress((void**)&deg,  g_deg);

    int M = NN;
    int gemm_grid = (M + BM - 1) / BM;

    zero_kernel<<<(NN * HID + 255) / 256, 256>>>();
    scatter_kernel<<<(EE + 7) / 8, 256>>>(ei, adj);
    rdeg_kernel<<<(NN + 255) / 256, 256>>>();

    // x branch
    gemm_n128<1><<<gemm_grid, 256>>>(x,   wx1, bx1, tmp,        M, INDIM, HID,     nullptr, nullptr);
    gemm_n128<0><<<gemm_grid, 256>>>(tmp, wx2, bx2, comb,       M, HID,   2 * HID, nullptr, nullptr);
    // adjacency branch (mean-normalization fused via rowscale)
    gemm_n128<1><<<gemm_grid, 256>>>(agg, wa1, ba1, tmp,        M, HID,   HID,     deg,     nullptr);
    gemm_n128<0><<<gemm_grid, 256>>>(tmp, wa2, ba2, comb + HID, M, HID,   2 * HID, nullptr, nullptr);
    // concat MLP + residual + relu chain
    gemm_n128<2><<<gemm_grid, 256>>>(comb, ww1, bw1, h,         M, 2 * HID, HID,   nullptr, comb);
    // classifier
    gemm_n40<<<(M + 63) / 64, 256>>>(h, wc, bc, out, M);
}

// round 5
// speedup vs baseline: 1.5320x; 1.5320x over previous
#include <cuda_runtime.h>
#include <cuda_bf16.h>
#include <cstdint>
#include <cstddef>

// LINKX forward, mma.sync(tf32) edition (tcgen05 unavailable: harness compiles
// via compute_103 virtual arch, which rejects 'a'-suffix features).
//   hx = relu(x@wx1+bx1)@wx2+bx2
//   agg = segment_mean(adj_embed[src] -> dst)
//   ha = relu(agg@wa1+ba1)@wa2+ba2
//   h = relu(relu([hx,ha]@ww1+bw1) + hx + ha)
//   out = h@wc+bc

#define NN     100000
#define EE     1600000
#define INDIM  256
#define HID    128
#define NC     40

// ---------------- static scratch ----------------
__device__ float g_tmp [(size_t)NN * HID];
__device__ float g_comb[(size_t)NN * 2 * HID];
__device__ float g_agg [(size_t)NN * HID];
__device__ float g_h   [(size_t)NN * HID];
__device__ float g_deg [NN];
__device__ float g_wt  [128 * (INDIM + HID + HID + HID + 2 * HID)]; // transposed tf32 weights

// ---------------- helpers ----------------
__device__ __forceinline__ float relu(float v) { return fmaxf(v, 0.0f); }

__device__ __forceinline__ void red_add_v4(float* addr, float4 v) {
    asm volatile("red.global.add.v4.f32 [%0], {%1,%2,%3,%4};"
                 :: "l"(addr), "f"(v.x), "f"(v.y), "f"(v.z), "f"(v.w)
                 : "memory");
}

__device__ __forceinline__ uint32_t tf32r(float f) {   // round-to-nearest tf32
    uint32_t r; asm("cvt.rna.tf32.f32 %0, %1;" : "=r"(r) : "f"(f)); return r;
}

// m16n8k8 tf32 MMA, fp32 accum
__device__ __forceinline__ void mma8(float* d, const uint32_t* a, const uint32_t* b) {
    asm volatile("mma.sync.aligned.m16n8k8.row.col.f32.tf32.tf32.f32 "
                 "{%0,%1,%2,%3}, {%4,%5,%6,%7}, {%8,%9}, {%0,%1,%2,%3};"
                 : "+f"(d[0]), "+f"(d[1]), "+f"(d[2]), "+f"(d[3])
                 : "r"(a[0]), "r"(a[1]), "r"(a[2]), "r"(a[3]),
                   "r"(b[0]), "r"(b[1]));
}

// ---------------- aggregation kernels ----------------
__global__ void zero_kernel() {
    int idx = blockIdx.x * blockDim.x + threadIdx.x;
    if (idx < NN * HID) g_agg[idx] = 0.0f;
    if (idx < NN) g_deg[idx] = 0.0f;
}

__global__ void scatter_kernel(const int* __restrict__ ei,
                               const float* __restrict__ z) {
    int gw   = (blockIdx.x * blockDim.x + threadIdx.x) >> 5;
    int lane = threadIdx.x & 31;
    if (gw >= EE) return;
    int s = ei[gw];
    int d = ei[EE + gw];
    float4 v = *((const float4*)(z + (size_t)s * HID) + lane);
    red_add_v4(g_agg + (size_t)d * HID + lane * 4, v);
    if (lane == 0) atomicAdd(&g_deg[d], 1.0f);
}

__global__ void rdeg_kernel() {
    int i = blockIdx.x * blockDim.x + threadIdx.x;
    if (i < NN) g_deg[i] = 1.0f / fmaxf(g_deg[i], 1.0f);
}

// ---------------- weight transpose + tf32 round: W[K,128] -> WT[128,K] ------
__global__ void transpose_w(const float* __restrict__ W, float* __restrict__ WT, int K) {
    int idx = blockIdx.x * blockDim.x + threadIdx.x;
    if (idx >= K * 128) return;
    int k = idx >> 7;
    int n = idx & 127;
    ((uint32_t*)WT)[(size_t)n * K + k] = tf32r(W[idx]);
}

// ---------------- tf32 mma.sync GEMM: [M,K] @ [K,128] -> [M,128] ------------
// CTA: 256 thr = 8 warps (4x2). CTA tile 128x128, warp tile 32x64.
// Shared holds fragment-packed tiles so fragment loads are LDS.128 / LDS.64.
//   A pack: float idx = ((s*8+mt)*32 + lane)*4 + slot   (s=k8-step, mt=m-tile)
//           lane = (r%8)*4 + (k%4);  slot = ((r/8)%2) | (((k/4)%2)<<1)
//   B pack: float idx = ((s*16+nt)*32 + lane)*2 + slot  (nt=n-tile)
//           lane = (n%8)*4 + (k%4);  slot = (k/4)%2
// MODE 0: C = acc + bias
// MODE 1: C = relu(acc + bias)
// MODE 2: C = relu(relu(acc + bias) + res[r][c] + res[r][c+128])  (res ld=256)
#define TG_SMEM 65536   // 2 x (A 16KB + B 16KB)

template <int MODE>
__global__ __launch_bounds__(256)
void tgemm(const float* __restrict__ A, const float* __restrict__ WT,
           const float* __restrict__ bias, float* __restrict__ C,
           int M, int K, int ldc,
           const float* __restrict__ rowscale, const float* __restrict__ res) {
    extern __shared__ float sm[];
    // layout: A0[0,4096) B0[4096,8192) A1[8192,12288) B1[12288,16384)
    int tid  = threadIdx.x;
    int lane = tid & 31;
    int w    = tid >> 5;
    int wm   = w >> 1;          // 0..3
    int wn   = w & 1;           // 0..1
    int row_base = blockIdx.x * 128;

    float acc[2][8][4];
#pragma unroll
    for (int i = 0; i < 2; i++)
#pragma unroll
        for (int j = 0; j < 8; j++)
#pragma unroll
            for (int q = 0; q < 4; q++) acc[i][j][q] = 0.0f;

    // per-thread writer indices (constant across chunks)
    int wf_r[4], wf_c4[4];
#pragma unroll
    for (int i = 0; i < 4; i++) {
        int f = tid + i * 256;
        wf_r[i]  = f >> 3;          // 0..127 (A row / B col)
        wf_c4[i] = (f & 7) << 2;    // k offset within chunk: 0,4,...,28
    }

    float4 stA[4];
    uint4  stB[4];

    int nchunk = K >> 5;

    auto load_chunk = [&](int c) {
#pragma unroll
        for (int i = 0; i < 4; i++) {
            int gr = row_base + wf_r[i];
            float4 v = make_float4(0.f, 0.f, 0.f, 0.f);
            if (gr < M) {
                v = *(const float4*)(A + (size_t)gr * K + (c << 5) + wf_c4[i]);
                if (rowscale) {
                    float s = rowscale[gr];
                    v.x *= s; v.y *= s; v.z *= s; v.w *= s;
                }
            }
            stA[i] = v;
            stB[i] = *(const uint4*)((const uint32_t*)WT +
                                     (size_t)wf_r[i] * K + (c << 5) + wf_c4[i]);
        }
    };

    auto store_chunk = [&](int b) {
        float* Ab = sm + b * 8192;
        float* Bb = sm + b * 8192 + 4096;
#pragma unroll
        for (int i = 0; i < 4; i++) {
            int r = wf_r[i], c4 = wf_c4[i];
            int s = c4 >> 3;
            int sh = (c4 >> 2) & 1;
            {   // A
                int mt = r >> 4;
                int slot = ((r >> 3) & 1) | (sh << 1);
                float* base = Ab + (s * 8 + mt) * 128 + (r & 7) * 16 + slot;
                base[0]  = __uint_as_float(tf32r(stA[i].x));
                base[4]  = __uint_as_float(tf32r(stA[i].y));
                base[8]  = __uint_as_float(tf32r(stA[i].z));
                base[12] = __uint_as_float(tf32r(stA[i].w));
            }
            {   // B (already tf32 bits)
                int nt = r >> 3;
                float* base = Bb + (s * 16 + nt) * 64 + (r & 7) * 8 + sh;
                base[0] = __uint_as_float(stB[i].x);
                base[2] = __uint_as_float(stB[i].y);
                base[4] = __uint_as_float(stB[i].z);
                base[6] = __uint_as_float(stB[i].w);
            }
        }
    };

    load_chunk(0);
    store_chunk(0);
    __syncthreads();

    for (int c = 0; c < nchunk; c++) {
        int b = c & 1;
        if (c + 1 < nchunk) load_chunk(c + 1);

        const float* Ab = sm + b * 8192;
        const float* Bb = sm + b * 8192 + 4096;
#pragma unroll
        for (int s = 0; s < 4; s++) {
            uint4 af[2];
#pragma unroll
            for (int mt = 0; mt < 2; mt++)
                af[mt] = *(const uint4*)(Ab + ((s * 8 + wm * 2 + mt) * 32 + lane) * 4);
            uint2 bf[8];
#pragma unroll
            for (int nt = 0; nt < 8; nt++)
                bf[nt] = *(const uint2*)(Bb + ((s * 16 + wn * 8 + nt) * 32 + lane) * 2);
#pragma unroll
            for (int mt = 0; mt < 2; mt++)
#pragma unroll
                for (int nt = 0; nt < 8; nt++)
                    mma8(acc[mt][nt], (const uint32_t*)&af[mt], (const uint32_t*)&bf[nt]);
        }

        if (c + 1 < nchunk) store_chunk((c + 1) & 1);
        __syncthreads();
    }

    // ---------------- epilogue ----------------
    int groupID = lane >> 2;
    int tq      = lane & 3;
#pragma unroll
    for (int mt = 0; mt < 2; mt++) {
        int r0 = row_base + wm * 32 + mt * 16 + groupID;   // rows r0, r0+8
#pragma unroll
        for (int nt = 0; nt < 8; nt++) {
            int col = wn * 64 + nt * 8 + tq * 2;
            float2 bv = *(const float2*)(bias + col);
            float o0x = acc[mt][nt][0] + bv.x;
            float o0y = acc[mt][nt][1] + bv.y;
            float o1x = acc[mt][nt][2] + bv.x;
            float o1y = acc[mt][nt][3] + bv.y;
            if (MODE >= 1) {
                o0x = relu(o0x); o0y = relu(o0y);
                o1x = relu(o1x); o1y = relu(o1y);
            }
            if (MODE == 2) {
                if (r0 < M) {
                    const float* rp = res + (size_t)r0 * 256 + col;
                    float2 r1 = *(const float2*)rp;
                    float2 r2 = *(const float2*)(rp + 128);
                    o0x = relu(o0x + r1.x + r2.x);
                    o0y = relu(o0y + r1.y + r2.y);
                }
                if (r0 + 8 < M) {
                    const float* rp = res + (size_t)(r0 + 8) * 256 + col;
                    float2 r1 = *(const float2*)rp;
                    float2 r2 = *(const float2*)(rp + 128);
                    o1x = relu(o1x + r1.x + r2.x);
                    o1y = relu(o1y + r1.y + r2.y);
                }
            }
            if (r0 < M)
                *(float2*)(C + (size_t)r0 * ldc + col) = make_float2(o0x, o0y);
            if (r0 + 8 < M)
                *(float2*)(C + (size_t)(r0 + 8) * ldc + col) = make_float2(o1x, o1y);
        }
    }
}

// ---------------- classifier GEMM: [M,128] @ [128,40] + b (SIMT) ------------
__global__ __launch_bounds__(256, 2)
void gemm_n40(const float* __restrict__ A, const float* __restrict__ W,
              const float* __restrict__ bias, float* __restrict__ C, int M) {
    __shared__ float As[64][132];
    __shared__ float Ws[128 * 40];
    __shared__ float bs[40];

    int tid = threadIdx.x;
    int br  = blockIdx.x * 64;

    for (int i = tid; i < 128 * 40; i += 256) Ws[i] = W[i];
    if (tid < 40) bs[tid] = bias[tid];
    for (int i = tid; i < 64 * 32; i += 256) {
        int r  = i >> 5;
        int c4 = (i & 31) * 4;
        int gr = br + r;
        float4 v = make_float4(0.f, 0.f, 0.f, 0.f);
        if (gr < M) v = *(const float4*)(A + (size_t)gr * HID + c4);
        *(float4*)&As[r][c4] = v;
    }
    __syncthreads();

    int r = tid >> 2;
    int q = tid & 3;
    float acc[10];
#pragma unroll
    for (int j = 0; j < 10; j++) acc[j] = 0.0f;

    for (int k = 0; k < 128; k += 4) {
        float4 a = *(const float4*)&As[r][k];
        float av[4] = {a.x, a.y, a.z, a.w};
#pragma unroll
        for (int kk = 0; kk < 4; kk++) {
            const float* wrow = &Ws[(k + kk) * 40 + q * 10];
#pragma unroll
            for (int j = 0; j < 10; j++)
                acc[j] = fmaf(av[kk], wrow[j], acc[j]);
        }
    }

    int gr = br + r;
    if (gr < M) {
        float* o = C + (size_t)gr * NC + q * 10;
#pragma unroll
        for (int j = 0; j < 10; j++) o[j] = acc[j] + bs[q * 10 + j];
    }
}

// ---------------- host launch ----------------
extern "C" void kernel_launch(void* const* d_in, const int* in_sizes, int n_in,
                              void* d_out, int out_size) {
    const float* x    = (const float*)d_in[0];
    const int*   ei   = (const int*)  d_in[1];
    const float* adj  = (const float*)d_in[2];
    const float* wx1  = (const float*)d_in[3];
    const float* bx1  = (const float*)d_in[4];
    const float* wx2  = (const float*)d_in[5];
    const float* bx2  = (const float*)d_in[6];
    const float* wa1  = (const float*)d_in[7];
    const float* ba1  = (const float*)d_in[8];
    const float* wa2  = (const float*)d_in[9];
    const float* ba2  = (const float*)d_in[10];
    const float* ww1  = (const float*)d_in[11];
    const float* bw1  = (const float*)d_in[12];
    const float* wc   = (const float*)d_in[13];
    const float* bc   = (const float*)d_in[14];
    float* out = (float*)d_out;

    float *tmp, *comb, *agg, *h, *deg, *wt;
    cudaGetSymbolAddress((void**)&tmp,  g_tmp);
    cudaGetSymbolAddress((void**)&comb, g_comb);
    cudaGetSymbolAddress((void**)&agg,  g_agg);
    cudaGetSymbolAddress((void**)&h,    g_h);
    cudaGetSymbolAddress((void**)&deg,  g_deg);
    cudaGetSymbolAddress((void**)&wt,   g_wt);

    float* wx1t = wt;              // 128*256
    float* wx2t = wt + 32768;      // 128*128
    float* wa1t = wt + 49152;      // 128*128
    float* wa2t = wt + 65536;      // 128*128
    float* ww1t = wt + 81920;      // 128*256

    cudaFuncSetAttribute(tgemm<0>, cudaFuncAttributeMaxDynamicSharedMemorySize, TG_SMEM);
    cudaFuncSetAttribute(tgemm<1>, cudaFuncAttributeMaxDynamicSharedMemorySize, TG_SMEM);
    cudaFuncSetAttribute(tgemm<2>, cudaFuncAttributeMaxDynamicSharedMemorySize, TG_SMEM);

    int M = NN;
    int grid = (M + 127) / 128;

    // weight prep (tiny)
    transpose_w<<<(INDIM * 128 + 255) / 256, 256>>>(wx1, wx1t, INDIM);
    transpose_w<<<(HID   * 128 + 255) / 256, 256>>>(wx2, wx2t, HID);
    transpose_w<<<(HID   * 128 + 255) / 256, 256>>>(wa1, wa1t, HID);
    transpose_w<<<(HID   * 128 + 255) / 256, 256>>>(wa2, wa2t, HID);
    transpose_w<<<(2*HID * 128 + 255) / 256, 256>>>(ww1, ww1t, 2 * HID);

    // aggregation
    zero_kernel<<<(NN * HID + 255) / 256, 256>>>();
    scatter_kernel<<<(EE + 7) / 8, 256>>>(ei, adj);
    rdeg_kernel<<<(NN + 255) / 256, 256>>>();

    // x branch
    tgemm<1><<<grid, 256, TG_SMEM>>>(x,   wx1t, bx1, tmp,        M, INDIM,   HID,     nullptr, nullptr);
    tgemm<0><<<grid, 256, TG_SMEM>>>(tmp, wx2t, bx2, comb,       M, HID,     2 * HID, nullptr, nullptr);
    // adjacency branch (mean-normalization fused via rowscale)
    tgemm<1><<<grid, 256, TG_SMEM>>>(agg, wa1t, ba1, tmp,        M, HID,     HID,     deg,     nullptr);
    tgemm<0><<<grid, 256, TG_SMEM>>>(tmp, wa2t, ba2, comb + HID, M, HID,     2 * HID, nullptr, nullptr);
    // concat MLP + residual + relu chain
    tgemm<2><<<grid, 256, TG_SMEM>>>(comb, ww1t, bw1, h,         M, 2 * HID, HID,     nullptr, comb);
    // classifier
    gemm_n40<<<(M + 63) / 64, 256>>>(h, wc, bc, out, M);
}

// round 6
// speedup vs baseline: 2.3978x; 1.5652x over previous
#include <cuda_runtime.h>
#include <cuda_bf16.h>
#include <cstdint>
#include <cstddef>

// LINKX forward, fused mma.sync(tf32) + CSR-gather edition.
//   hx = relu(x@wx1+bx1)@wx2+bx2
//   agg = segment_mean(adj_embed[src] -> dst)      (CSR build + gather)
//   ha = relu(agg@wa1+ba1)@wa2+ba2
//   h  = relu(relu([hx,ha]@ww1+bw1) + hx + ha)
//   out = h@wc+bc

#define NN     100000
#define EE     1600000
#define INDIM  256
#define HID    128
#define NC     40

#define NBLK_SCAN 98   // ceil(NN/1024)

// ---------------- static scratch ----------------
__device__ float g_comb[(size_t)NN * 2 * HID]; // [hx | ha]
__device__ float g_agg [(size_t)NN * HID];     // pre-normalized neighbour mean
__device__ float g_wp  [119808];               // packed tf32 weights
__device__ int   g_cnt [NN];
__device__ int   g_start[NN];
__device__ int   g_cur [NN];
__device__ int   g_bsum[NBLK_SCAN];
__device__ int   g_srcs[EE];

// packed-weight float offsets
#define WP_X1 0
#define WP_X2 32768
#define WP_A1 49152
#define WP_A2 65536
#define WP_W1 81920
#define WP_C  114688

// ---------------- helpers ----------------
__device__ __forceinline__ float relu(float v) { return fmaxf(v, 0.0f); }

__device__ __forceinline__ uint32_t tf32r(float f) {   // round-to-nearest tf32
    uint32_t r; asm("cvt.rna.tf32.f32 %0, %1;" : "=r"(r) : "f"(f)); return r;
}

// m16n8k8 tf32 MMA, fp32 accum
__device__ __forceinline__ void mma8(float* d, const uint32_t* a, const uint32_t* b) {
    asm volatile("mma.sync.aligned.m16n8k8.row.col.f32.tf32.tf32.f32 "
                 "{%0,%1,%2,%3}, {%4,%5,%6,%7}, {%8,%9}, {%0,%1,%2,%3};"
                 : "+f"(d[0]), "+f"(d[1]), "+f"(d[2]), "+f"(d[3])
                 : "r"(a[0]), "r"(a[1]), "r"(a[2]), "r"(a[3]),
                   "r"(b[0]), "r"(b[1]));
}

// write one fp32 value (tf32-rounded) into fragment-packed A layout (128x128)
__device__ __forceinline__ void packA(float* P, int R, int Ck, float v) {
    int s = Ck >> 3, j = Ck & 3, sh = (Ck >> 2) & 1;
    int o = ((s * 8 + (R >> 4)) * 32 + (R & 7) * 4 + j) * 4
          + (((R >> 3) & 1) | (sh << 1));
    P[o] = __uint_as_float(tf32r(v));
}

// ---------------- weight packing (B-fragment layout) ----------------
// idx = ((s*16+nt)*32 + (n&7)*4 + (k&3))*2 + ((k>>2)&1),  s = k>>3, nt = n>>3
__global__ void pack_w(const float* __restrict__ W, float* __restrict__ P, int K) {
    int idx = blockIdx.x * blockDim.x + threadIdx.x;
    if (idx >= K * 128) return;
    int k = idx >> 7, n = idx & 127;
    int o = (((k >> 3) * 16 + (n >> 3)) * 32 + (n & 7) * 4 + (k & 3)) * 2
          + ((k >> 2) & 1);
    P[o] = __uint_as_float(tf32r(W[idx]));
}

__global__ void pack_wc(const float* __restrict__ W, float* __restrict__ P) {
    int idx = blockIdx.x * blockDim.x + threadIdx.x;
    if (idx >= 128 * 40) return;
    int k = idx / 40, n = idx % 40;
    int o = (((k >> 3) * 5 + (n >> 3)) * 32 + (n & 7) * 4 + (k & 3)) * 2
          + ((k >> 2) & 1);
    P[o] = __uint_as_float(tf32r(W[idx]));
}

// ---------------- CSR build ----------------
__global__ void zero_cnt() {
    int i = blockIdx.x * blockDim.x + threadIdx.x;
    if (i < NN) g_cnt[i] = 0;
}

__global__ void hist_kernel(const int* __restrict__ ei) {
    int e = blockIdx.x * blockDim.x + threadIdx.x;
    if (e < EE) atomicAdd(&g_cnt[ei[EE + e]], 1);
}

__global__ void scan1() {               // block-inclusive scan, 1024 threads
    __shared__ int sh[1024];
    int t  = threadIdx.x;
    int gi = blockIdx.x * 1024 + t;
    int v  = (gi < NN) ? g_cnt[gi] : 0;
    sh[t] = v;
    __syncthreads();
#pragma unroll
    for (int o = 1; o < 1024; o <<= 1) {
        int u = (t >= o) ? sh[t - o] : 0;
        __syncthreads();
        sh[t] += u;
        __syncthreads();
    }
    if (gi < NN) g_start[gi] = sh[t];        // inclusive for now
    if (t == 1023) g_bsum[blockIdx.x] = sh[1023];
}

__global__ void scan2() {               // exclusive scan of 98 block sums
    if (threadIdx.x == 0) {
        int acc = 0;
        for (int i = 0; i < NBLK_SCAN; i++) {
            int v = g_bsum[i]; g_bsum[i] = acc; acc += v;
        }
    }
}

__global__ void scan3() {               // exclusive start offsets + cursor
    int i = blockIdx.x * blockDim.x + threadIdx.x;
    if (i >= NN) return;
    int st = g_start[i] + g_bsum[i >> 10] - g_cnt[i];
    g_start[i] = st;
    g_cur[i]   = st;
}

__global__ void fill_kernel(const int* __restrict__ ei) {
    int e = blockIdx.x * blockDim.x + threadIdx.x;
    if (e >= EE) return;
    int d = ei[EE + e];
    int p = atomicAdd(&g_cur[d], 1);
    g_srcs[p] = ei[e];
}

// ---------------- gather: one warp per node, pre-normalized mean ------------
__global__ __launch_bounds__(256)
void gather_kernel(const float* __restrict__ z) {
    int gw   = (blockIdx.x * blockDim.x + threadIdx.x) >> 5;
    int lane = threadIdx.x & 31;
    if (gw >= NN) return;
    int beg = g_start[gw];
    int dg  = g_cnt[gw];

    float4 a0 = make_float4(0.f, 0.f, 0.f, 0.f);
    float4 a1 = make_float4(0.f, 0.f, 0.f, 0.f);
    int e = 0;
    for (; e + 2 <= dg; e += 2) {
        int s0 = g_srcs[beg + e];
        int s1 = g_srcs[beg + e + 1];
        float4 v0 = *((const float4*)(z + (size_t)s0 * HID) + lane);
        float4 v1 = *((const float4*)(z + (size_t)s1 * HID) + lane);
        a0.x += v0.x; a0.y += v0.y; a0.z += v0.z; a0.w += v0.w;
        a1.x += v1.x; a1.y += v1.y; a1.z += v1.z; a1.w += v1.w;
    }
    if (e < dg) {
        int s0 = g_srcs[beg + e];
        float4 v0 = *((const float4*)(z + (size_t)s0 * HID) + lane);
        a0.x += v0.x; a0.y += v0.y; a0.z += v0.z; a0.w += v0.w;
    }
    float inv = 1.0f / (float)max(dg, 1);
    float4 o;
    o.x = (a0.x + a1.x) * inv;
    o.y = (a0.y + a1.y) * inv;
    o.z = (a0.z + a1.z) * inv;
    o.w = (a0.w + a1.w) * inv;
    *((float4*)(g_agg + (size_t)gw * HID) + lane) = o;
}

// ---------------- fused 2-layer MLP ----------------
// Cout[r][0..127] = relu(A@W1+b1)@W2 + b2    (A: [M,K1] stride K1, W packed)
// SMEM floats: Ab0 0, Bb0 4096, Ab1 8192, Bb1 12288, pack 16384, W2s 32768
#define MLP_SMEM (49152 * 4)

__global__ __launch_bounds__(256)
void fused_mlp(const float* __restrict__ A, const float* __restrict__ W1p,
               const float* __restrict__ b1, const float* __restrict__ W2p,
               const float* __restrict__ b2, float* __restrict__ Cout,
               int K1, int ldc) {
    extern __shared__ float sm[];
    float* Pk  = sm + 16384;
    float* W2s = sm + 32768;

    int tid  = threadIdx.x;
    int lane = tid & 31;
    int w    = tid >> 5;
    int wm   = w >> 1;
    int wn   = w & 1;
    int group = lane >> 2;
    int tq    = lane & 3;
    int row_base = blockIdx.x * 128;
    const int M = NN;

    // stage-2 weights -> SMEM (16384 floats)
#pragma unroll
    for (int i = 0; i < 16; i++)
        ((uint4*)W2s)[tid + i * 256] = ((const uint4*)W2p)[tid + i * 256];

    float acc[2][8][4];
#pragma unroll
    for (int i = 0; i < 2; i++)
#pragma unroll
        for (int j = 0; j < 8; j++)
#pragma unroll
            for (int q = 0; q < 4; q++) acc[i][j][q] = 0.0f;

    int wf_r[4], wf_c4[4];
#pragma unroll
    for (int i = 0; i < 4; i++) {
        int f = tid + i * 256;
        wf_r[i]  = f >> 3;
        wf_c4[i] = (f & 7) << 2;
    }

    float4 stA[4];
    uint4  stB[4];
    int nchunk = K1 >> 5;

    auto load_chunk = [&](int c) {
#pragma unroll
        for (int i = 0; i < 4; i++) {
            int gr = row_base + wf_r[i];
            float4 v = make_float4(0.f, 0.f, 0.f, 0.f);
            if (gr < M)
                v = *(const float4*)(A + (size_t)gr * K1 + (c << 5) + wf_c4[i]);
            stA[i] = v;
        }
        const uint4* bsrc = (const uint4*)(W1p + c * 4096);
#pragma unroll
        for (int i = 0; i < 4; i++) stB[i] = bsrc[tid + i * 256];
    };

    auto store_chunk = [&](int b) {
        float* Ab = sm + b * 8192;
        float* Bb = sm + b * 8192 + 4096;
#pragma unroll
        for (int i = 0; i < 4; i++) {
            int r = wf_r[i], c4 = wf_c4[i];
            int s = c4 >> 3;
            int sh = (c4 >> 2) & 1;
            int mt = r >> 4;
            int slot = ((r >> 3) & 1) | (sh << 1);
            float* base = Ab + (s * 8 + mt) * 128 + (r & 7) * 16 + slot;
            base[0]  = __uint_as_float(tf32r(stA[i].x));
            base[4]  = __uint_as_float(tf32r(stA[i].y));
            base[8]  = __uint_as_float(tf32r(stA[i].z));
            base[12] = __uint_as_float(tf32r(stA[i].w));
            ((uint4*)Bb)[tid + i * 256] = stB[i];
        }
    };

    load_chunk(0);
    store_chunk(0);
    __syncthreads();

    for (int c = 0; c < nchunk; c++) {
        int b = c & 1;
        if (c + 1 < nchunk) load_chunk(c + 1);

        const float* Ab = sm + b * 8192;
        const float* Bb = sm + b * 8192 + 4096;
#pragma unroll
        for (int s = 0; s < 4; s++) {
            uint4 af[2];
#pragma unroll
            for (int mt = 0; mt < 2; mt++)
                af[mt] = *(const uint4*)(Ab + ((s * 8 + wm * 2 + mt) * 32 + lane) * 4);
            uint2 bf[8];
#pragma unroll
            for (int nt = 0; nt < 8; nt++)
                bf[nt] = *(const uint2*)(Bb + ((s * 16 + wn * 8 + nt) * 32 + lane) * 2);
#pragma unroll
            for (int mt = 0; mt < 2; mt++)
#pragma unroll
                for (int nt = 0; nt < 8; nt++)
                    mma8(acc[mt][nt], (const uint32_t*)&af[mt], (const uint32_t*)&bf[nt]);
        }

        if (c + 1 < nchunk) store_chunk((c + 1) & 1);
        __syncthreads();
    }

    // stage-1 epilogue: relu(acc+b1) -> fragment-packed SMEM (tf32)
#pragma unroll
    for (int mt = 0; mt < 2; mt++) {
        int Rb = wm * 32 + mt * 16 + group;            // local rows Rb, Rb+8
#pragma unroll
        for (int nt = 0; nt < 8; nt++) {
            int col = wn * 64 + nt * 8 + tq * 2;
            float2 bv = *(const float2*)(b1 + col);
            packA(Pk, Rb,     col,     relu(acc[mt][nt][0] + bv.x));
            packA(Pk, Rb,     col + 1, relu(acc[mt][nt][1] + bv.y));
            packA(Pk, Rb + 8, col,     relu(acc[mt][nt][2] + bv.x));
            packA(Pk, Rb + 8, col + 1, relu(acc[mt][nt][3] + bv.y));
        }
    }
    __syncthreads();

    // stage 2: packed A (K=128) @ W2s
    float acc2[2][8][4];
#pragma unroll
    for (int i = 0; i < 2; i++)
#pragma unroll
        for (int j = 0; j < 8; j++)
#pragma unroll
            for (int q = 0; q < 4; q++) acc2[i][j][q] = 0.0f;

#pragma unroll
    for (int s = 0; s < 16; s++) {
        uint4 af[2];
#pragma unroll
        for (int mt = 0; mt < 2; mt++)
            af[mt] = *(const uint4*)(Pk + ((s * 8 + wm * 2 + mt) * 32 + lane) * 4);
        uint2 bf[8];
#pragma unroll
        for (int nt = 0; nt < 8; nt++)
            bf[nt] = *(const uint2*)(W2s + ((s * 16 + wn * 8 + nt) * 32 + lane) * 2);
#pragma unroll
        for (int mt = 0; mt < 2; mt++)
#pragma unroll
            for (int nt = 0; nt < 8; nt++)
                mma8(acc2[mt][nt], (const uint32_t*)&af[mt], (const uint32_t*)&bf[nt]);
    }

    // stage-2 epilogue: + b2, store to Cout
#pragma unroll
    for (int mt = 0; mt < 2; mt++) {
        int r0 = row_base + wm * 32 + mt * 16 + group;
#pragma unroll
        for (int nt = 0; nt < 8; nt++) {
            int col = wn * 64 + nt * 8 + tq * 2;
            float2 bv = *(const float2*)(b2 + col);
            if (r0 < M)
                *(float2*)(Cout + (size_t)r0 * ldc + col) =
                    make_float2(acc2[mt][nt][0] + bv.x, acc2[mt][nt][1] + bv.y);
            if (r0 + 8 < M)
                *(float2*)(Cout + (size_t)(r0 + 8) * ldc + col) =
                    make_float2(acc2[mt][nt][2] + bv.x, acc2[mt][nt][3] + bv.y);
        }
    }
}

// ---------------- fused final: concat-MLP + residual + classifier ----------
// h = relu(relu(comb@ww1+bw1) + comb[:, :128] + comb[:, 128:]); out = h@wc+bc
// SMEM floats: Ab0 0, Bb0 4096, Ab1 8192, Bb1 12288, pack 16384, Wc 32768
#define FIN_SMEM ((32768 + 5120) * 4)

__global__ __launch_bounds__(256)
void fused_final(const float* __restrict__ comb, const float* __restrict__ W1p,
                 const float* __restrict__ b1, const float* __restrict__ Wcp,
                 const float* __restrict__ bc, float* __restrict__ out) {
    extern __shared__ float sm[];
    float* Pk  = sm + 16384;
    float* Wcs = sm + 32768;

    int tid  = threadIdx.x;
    int lane = tid & 31;
    int w    = tid >> 5;
    int wm   = w >> 1;
    int wn   = w & 1;
    int group = lane >> 2;
    int tq    = lane & 3;
    int row_base = blockIdx.x * 128;
    const int M = NN;
    const int K1 = 256;

    // classifier weights -> SMEM (5120 floats = 1280 uint4)
#pragma unroll
    for (int i = 0; i < 5; i++)
        ((uint4*)Wcs)[tid + i * 256] = ((const uint4*)Wcp)[tid + i * 256];

    float acc[2][8][4];
#pragma unroll
    for (int i = 0; i < 2; i++)
#pragma unroll
        for (int j = 0; j < 8; j++)
#pragma unroll
            for (int q = 0; q < 4; q++) acc[i][j][q] = 0.0f;

    int wf_r[4], wf_c4[4];
#pragma unroll
    for (int i = 0; i < 4; i++) {
        int f = tid + i * 256;
        wf_r[i]  = f >> 3;
        wf_c4[i] = (f & 7) << 2;
    }

    float4 stA[4];
    uint4  stB[4];
    const int nchunk = 8;

    auto load_chunk = [&](int c) {
#pragma unroll
        for (int i = 0; i < 4; i++) {
            int gr = row_base + wf_r[i];
            float4 v = make_float4(0.f, 0.f, 0.f, 0.f);
            if (gr < M)
                v = *(const float4*)(comb + (size_t)gr * K1 + (c << 5) + wf_c4[i]);
            stA[i] = v;
        }
        const uint4* bsrc = (const uint4*)(W1p + c * 4096);
#pragma unroll
        for (int i = 0; i < 4; i++) stB[i] = bsrc[tid + i * 256];
    };

    auto store_chunk = [&](int b) {
        float* Ab = sm + b * 8192;
        float* Bb = sm + b * 8192 + 4096;
#pragma unroll
        for (int i = 0; i < 4; i++) {
            int r = wf_r[i], c4 = wf_c4[i];
            int s = c4 >> 3;
            int sh = (c4 >> 2) & 1;
            int mt = r >> 4;
            int slot = ((r >> 3) & 1) | (sh << 1);
            float* base = Ab + (s * 8 + mt) * 128 + (r & 7) * 16 + slot;
            base[0]  = __uint_as_float(tf32r(stA[i].x));
            base[4]  = __uint_as_float(tf32r(stA[i].y));
            base[8]  = __uint_as_float(tf32r(stA[i].z));
            base[12] = __uint_as_float(tf32r(stA[i].w));
            ((uint4*)Bb)[tid + i * 256] = stB[i];
        }
    };

    load_chunk(0);
    store_chunk(0);
    __syncthreads();

    for (int c = 0; c < nchunk; c++) {
        int b = c & 1;
        if (c + 1 < nchunk) load_chunk(c + 1);

        const float* Ab = sm + b * 8192;
        const float* Bb = sm + b * 8192 + 4096;
#pragma unroll
        for (int s = 0; s < 4; s++) {
            uint4 af[2];
#pragma unroll
            for (int mt = 0; mt < 2; mt++)
                af[mt] = *(const uint4*)(Ab + ((s * 8 + wm * 2 + mt) * 32 + lane) * 4);
            uint2 bf[8];
#pragma unroll
            for (int nt = 0; nt < 8; nt++)
                bf[nt] = *(const uint2*)(Bb + ((s * 16 + wn * 8 + nt) * 32 + lane) * 2);
#pragma unroll
            for (int mt = 0; mt < 2; mt++)
#pragma unroll
                for (int nt = 0; nt < 8; nt++)
                    mma8(acc[mt][nt], (const uint32_t*)&af[mt], (const uint32_t*)&bf[nt]);
        }

        if (c + 1 < nchunk) store_chunk((c + 1) & 1);
        __syncthreads();
    }

    // epilogue: relu -> +residual -> relu -> pack (tf32) into SMEM
#pragma unroll
    for (int mt = 0; mt < 2; mt++) {
        int Rb = wm * 32 + mt * 16 + group;
        int r0 = row_base + Rb;
#pragma unroll
        for (int nt = 0; nt < 8; nt++) {
            int col = wn * 64 + nt * 8 + tq * 2;
            float2 bv = *(const float2*)(b1 + col);
            float v00 = relu(acc[mt][nt][0] + bv.x);
            float v01 = relu(acc[mt][nt][1] + bv.y);
            float v10 = relu(acc[mt][nt][2] + bv.x);
            float v11 = relu(acc[mt][nt][3] + bv.y);
            if (r0 < M) {
                const float* rp = comb + (size_t)r0 * 256 + col;
                float2 r1 = *(const float2*)rp;
                float2 r2 = *(const float2*)(rp + 128);
                v00 = relu(v00 + r1.x + r2.x);
                v01 = relu(v01 + r1.y + r2.y);
            }
            if (r0 + 8 < M) {
                const float* rp = comb + (size_t)(r0 + 8) * 256 + col;
                float2 r1 = *(const float2*)rp;
                float2 r2 = *(const float2*)(rp + 128);
                v10 = relu(v10 + r1.x + r2.x);
                v11 = relu(v11 + r1.y + r2.y);
            }
            packA(Pk, Rb,     col,     v00);
            packA(Pk, Rb,     col + 1, v01);
            packA(Pk, Rb + 8, col,     v10);
            packA(Pk, Rb + 8, col + 1, v11);
        }
    }
    __syncthreads();

    // classifier: warp w covers rows w*16..w*16+15; N=40 -> 5 n-tiles
    float acc3[5][4];
#pragma unroll
    for (int j = 0; j < 5; j++)
#pragma unroll
        for (int q = 0; q < 4; q++) acc3[j][q] = 0.0f;

#pragma unroll
    for (int s = 0; s < 16; s++) {
        uint4 af = *(const uint4*)(Pk + ((s * 8 + w) * 32 + lane) * 4);
        uint2 bf[5];
#pragma unroll
        for (int nt = 0; nt < 5; nt++)
            bf[nt] = *(const uint2*)(Wcs + ((s * 5 + nt) * 32 + lane) * 2);
#pragma unroll
        for (int nt = 0; nt < 5; nt++)
            mma8(acc3[nt], (const uint32_t*)&af, (const uint32_t*)&bf[nt]);
    }

    int r0 = row_base + w * 16 + group;
#pragma unroll
    for (int nt = 0; nt < 5; nt++) {
        int col = nt * 8 + tq * 2;
        float2 bv = *(const float2*)(bc + col);
        if (r0 < M)
            *(float2*)(out + (size_t)r0 * NC + col) =
                make_float2(acc3[nt][0] + bv.x, acc3[nt][1] + bv.y);
        if (r0 + 8 < M)
            *(float2*)(out + (size_t)(r0 + 8) * NC + col) =
                make_float2(acc3[nt][2] + bv.x, acc3[nt][3] + bv.y);
    }
}

// ---------------- host launch ----------------
extern "C" void kernel_launch(void* const* d_in, const int* in_sizes, int n_in,
                              void* d_out, int out_size) {
    const float* x    = (const float*)d_in[0];
    const int*   ei   = (const int*)  d_in[1];
    const float* adj  = (const float*)d_in[2];
    const float* wx1  = (const float*)d_in[3];
    const float* bx1  = (const float*)d_in[4];
    const float* wx2  = (const float*)d_in[5];
    const float* bx2  = (const float*)d_in[6];
    const float* wa1  = (const float*)d_in[7];
    const float* ba1  = (const float*)d_in[8];
    const float* wa2  = (const float*)d_in[9];
    const float* ba2  = (const float*)d_in[10];
    const float* ww1  = (const float*)d_in[11];
    const float* bw1  = (const float*)d_in[12];
    const float* wc   = (const float*)d_in[13];
    const float* bc   = (const float*)d_in[14];
    float* out = (float*)d_out;

    float *comb, *agg, *wp;
    cudaGetSymbolAddress((void**)&comb, g_comb);
    cudaGetSymbolAddress((void**)&agg,  g_agg);
    cudaGetSymbolAddress((void**)&wp,   g_wp);

    cudaFuncSetAttribute(fused_mlp,   cudaFuncAttributeMaxDynamicSharedMemorySize, MLP_SMEM);
    cudaFuncSetAttribute(fused_final, cudaFuncAttributeMaxDynamicSharedMemorySize, FIN_SMEM);

    int grid = (NN + 127) / 128;   // 782

    // ---- weight packing (tiny) ----
    pack_w <<<(INDIM * 128 + 255) / 256, 256>>>(wx1, wp + WP_X1, INDIM);
    pack_w <<<(HID   * 128 + 255) / 256, 256>>>(wx2, wp + WP_X2, HID);
    pack_w <<<(HID   * 128 + 255) / 256, 256>>>(wa1, wp + WP_A1, HID);
    pack_w <<<(HID   * 128 + 255) / 256, 256>>>(wa2, wp + WP_A2, HID);
    pack_w <<<(2*HID * 128 + 255) / 256, 256>>>(ww1, wp + WP_W1, 2 * HID);
    pack_wc<<<(128 * 40 + 255) / 256, 256>>>(wc, wp + WP_C);

    // ---- CSR build + gather ----
    zero_cnt   <<<(NN + 255) / 256, 256>>>();
    hist_kernel<<<(EE + 255) / 256, 256>>>(ei);
    scan1      <<<NBLK_SCAN, 1024>>>();
    scan2      <<<1, 32>>>();
    scan3      <<<(NN + 255) / 256, 256>>>();
    fill_kernel<<<(EE + 255) / 256, 256>>>(ei);
    gather_kernel<<<(NN * 32 + 255) / 256, 256>>>(adj);

    // ---- fused network ----
    fused_mlp<<<grid, 256, MLP_SMEM>>>(x,   wp + WP_X1, bx1, wp + WP_X2, bx2,
                                       comb,       INDIM, 2 * HID);
    fused_mlp<<<grid, 256, MLP_SMEM>>>(agg, wp + WP_A1, ba1, wp + WP_A2, ba2,
                                       comb + HID, HID,   2 * HID);
    fused_final<<<grid, 256, FIN_SMEM>>>(comb, wp + WP_W1, bw1, wp + WP_C, bc, out);
}